// round 3
// baseline (speedup 1.0000x reference)
#include <cuda_runtime.h>

// Fully fused quanvolution + linear + log_softmax.
// Key insight: the 9-qubit circuit factors into components {0},{1},{5},{2,3,4},{6,7,8};
// rz gates never affect Z-expectations; every feature has a closed trig form:
//   Z0 = cos(t0)cos(t9)cos d0 - sin(t9)sin d0     Z5 = cos(d5 + t5)
//   Z1 = cos(d1 + t1)                             Z6 = cos d6
//   Z2 = cos d2                                   Z7 = cos d6 cos d7
//   Z3 = cos(t12) cos d2 cos d3                   Z8 = cos(t8) cos d7 cos d8
//   Z4 = cos(t4)cos(t13)cos d3 cos d4 - sin(t13)sin d4

#define IMG_W 28
#define IMG_PIX 784
#define N_PATCH 169
#define FEAT 1521
#define NTHREADS 192

__global__ void __launch_bounds__(NTHREADS) quanv_fused_kernel(
    const float* __restrict__ x,     // [bsz, 28, 28]
    const float* __restrict__ qp,    // [16]
    const float* __restrict__ W,     // [2, 1521]
    const float* __restrict__ bias,  // [2]
    float* __restrict__ out)         // [bsz, 2]
{
    __shared__ float g[8];           // precomputed gate trig constants
    __shared__ float warp0[6], warp1[6];

    const int t   = threadIdx.x;
    const int img = blockIdx.x;

    if (t == 0) {
        const float th0  = qp[0],  th1  = qp[1];
        const float th4  = qp[4],  th5  = qp[5];
        const float th8  = qp[8],  th9  = qp[9];
        const float th12 = qp[12], th13 = qp[13];
        g[0] = cosf(th0) * cosf(th9);   // Z0 cos-term
        g[1] = sinf(th9);               // Z0 sin-term
        g[2] = th1;                     // Z1 phase shift
        g[3] = cosf(th12);              // Z3 factor
        g[4] = cosf(th4) * cosf(th13);  // Z4 cos-term
        g[5] = sinf(th13);              // Z4 sin-term
        g[6] = th5;                     // Z5 phase shift
        g[7] = cosf(th8);               // Z8 factor
    }
    __syncthreads();

    float s0 = 0.f, s1 = 0.f;

    if (t < N_PATCH) {
        const int pi = t / 13;
        const int pj = t - pi * 13;
        const float* xb = x + img * IMG_PIX + (2 * pi) * IMG_W + 2 * pj;

        float d[9];
        #pragma unroll
        for (int r = 0; r < 3; r++)
            #pragma unroll
            for (int c = 0; c < 3; c++)
                d[r * 3 + c] = __ldg(xb + r * IMG_W + c);

        float sd0, cd0, sd4, cd4;
        sincosf(d[0], &sd0, &cd0);
        sincosf(d[4], &sd4, &cd4);
        const float cd2 = cosf(d[2]);
        const float cd3 = cosf(d[3]);
        const float cd6 = cosf(d[6]);
        const float cd7 = cosf(d[7]);
        const float cd8 = cosf(d[8]);

        float z[9];
        z[0] = g[0] * cd0 - g[1] * sd0;
        z[1] = cosf(d[1] + g[2]);
        z[2] = cd2;
        z[3] = g[3] * cd2 * cd3;
        z[4] = g[4] * cd3 * cd4 - g[5] * sd4;
        z[5] = cosf(d[5] + g[6]);
        z[6] = cd6;
        z[7] = cd6 * cd7;
        z[8] = g[7] * cd7 * cd8;

        const float* w0 = W + t * 9;          // class 0 weights for this patch
        const float* w1 = W + FEAT + t * 9;   // class 1 weights
        #pragma unroll
        for (int k = 0; k < 9; k++) {
            s0 = fmaf(z[k], __ldg(w0 + k), s0);
            s1 = fmaf(z[k], __ldg(w1 + k), s1);
        }
    }

    // warp-level reduction of (s0, s1)
    #pragma unroll
    for (int off = 16; off > 0; off >>= 1) {
        s0 += __shfl_down_sync(0xffffffffu, s0, off);
        s1 += __shfl_down_sync(0xffffffffu, s1, off);
    }
    const int wid = t >> 5;
    if ((t & 31) == 0) { warp0[wid] = s0; warp1[wid] = s1; }
    __syncthreads();

    if (t == 0) {
        float l0 = bias[0], l1 = bias[1];
        #pragma unroll
        for (int i = 0; i < 6; i++) { l0 += warp0[i]; l1 += warp1[i]; }
        const float m   = fmaxf(l0, l1);
        const float lse = m + logf(expf(l0 - m) + expf(l1 - m));
        out[img * 2 + 0] = l0 - lse;
        out[img * 2 + 1] = l1 - lse;
    }
}

extern "C" void kernel_launch(void* const* d_in, const int* in_sizes, int n_in,
                              void* d_out, int out_size) {
    const float* x  = (const float*)d_in[0];
    const float* qp = (const float*)d_in[1];
    const float* W  = (const float*)d_in[2];
    const float* b  = (const float*)d_in[3];
    float* out = (float*)d_out;

    const int bsz = in_sizes[0] / IMG_PIX;   // 512
    quanv_fused_kernel<<<bsz, NTHREADS>>>(x, qp, W, b, out);
}

// round 4
// speedup vs baseline: 1.2537x; 1.2537x over previous
#include <cuda_runtime.h>

// Fully fused quanvolution + linear + log_softmax.
// Circuit factors into components {0},{1},{5},{2,3,4},{6,7,8}; rz gates never
// affect Z-expectations; every feature has a closed trig form:
//   Z0 = cos(t0)cos(t9)cos d0 - sin(t9)sin d0     Z5 = cos(d5 + t5)
//   Z1 = cos(d1 + t1)                             Z6 = cos d6
//   Z2 = cos d2                                   Z7 = cos d6 cos d7
//   Z3 = cos(t12) cos d2 cos d3                   Z8 = cos(t8) cos d7 cos d8
//   Z4 = cos(t4)cos(t13)cos d3 cos d4 - sin(t13)sin d4
// Latency-bound (occ capped ~32% by total work) -> shorten per-block critical
// path: coalesced float4 staging of the image into smem + MUFU fast trig.

#define IMG_W 28
#define IMG_PIX 784
#define N_PATCH 169
#define FEAT 1521
#define NTHREADS 192

__global__ void __launch_bounds__(NTHREADS) quanv_fused_kernel(
    const float* __restrict__ x,     // [bsz, 28, 28]
    const float* __restrict__ qp,    // [16]
    const float* __restrict__ W,     // [2, 1521]
    const float* __restrict__ bias,  // [2]
    float* __restrict__ out)         // [bsz, 2]
{
    __shared__ __align__(16) float sx[IMG_PIX];  // staged image
    __shared__ float g[10];                      // gate trig constants
    __shared__ float warp0[6], warp1[6];

    const int t   = threadIdx.x;
    const int img = blockIdx.x;

    // Coalesced staging: 784 floats = 196 float4 loads
    {
        const float4* src = (const float4*)(x + img * IMG_PIX);
        float4* dst = (float4*)sx;
        dst[t] = __ldg(src + t);
        if (t < 196 - NTHREADS) dst[NTHREADS + t] = __ldg(src + NTHREADS + t);
    }

    if (t == 0) {
        const float th0  = qp[0],  th1  = qp[1];
        const float th4  = qp[4],  th5  = qp[5];
        const float th8  = qp[8],  th9  = qp[9];
        const float th12 = qp[12], th13 = qp[13];
        float s1g, c1g, s5g, c5g;
        __sincosf(th1, &s1g, &c1g);
        __sincosf(th5, &s5g, &c5g);
        g[0] = __cosf(th0) * __cosf(th9);    // Z0 cos-term
        g[1] = __sinf(th9);                  // Z0 sin-term
        g[2] = c1g;                          // cos t1
        g[3] = s1g;                          // sin t1
        g[4] = __cosf(th12);                 // Z3 factor
        g[5] = __cosf(th4) * __cosf(th13);   // Z4 cos-term
        g[6] = __sinf(th13);                 // Z4 sin-term
        g[7] = c5g;                          // cos t5
        g[8] = s5g;                          // sin t5
        g[9] = __cosf(th8);                  // Z8 factor
    }
    __syncthreads();

    float s0 = 0.f, s1 = 0.f;

    if (t < N_PATCH) {
        const int pi = t / 13;
        const int pj = t - pi * 13;
        const float* xb = sx + (2 * pi) * IMG_W + 2 * pj;

        const float d0 = xb[0],              d1 = xb[1],              d2 = xb[2];
        const float d3 = xb[IMG_W],          d4 = xb[IMG_W + 1],      d5 = xb[IMG_W + 2];
        const float d6 = xb[2 * IMG_W],      d7 = xb[2 * IMG_W + 1],  d8 = xb[2 * IMG_W + 2];

        float sd0, cd0, sd1, cd1, sd4, cd4, sd5, cd5;
        __sincosf(d0, &sd0, &cd0);
        __sincosf(d1, &sd1, &cd1);
        __sincosf(d4, &sd4, &cd4);
        __sincosf(d5, &sd5, &cd5);
        const float cd2 = __cosf(d2);
        const float cd3 = __cosf(d3);
        const float cd6 = __cosf(d6);
        const float cd7 = __cosf(d7);
        const float cd8 = __cosf(d8);

        float z[9];
        z[0] = g[0] * cd0 - g[1] * sd0;
        z[1] = g[2] * cd1 - g[3] * sd1;      // cos(d1 + t1)
        z[2] = cd2;
        z[3] = g[4] * cd2 * cd3;
        z[4] = g[5] * cd3 * cd4 - g[6] * sd4;
        z[5] = g[7] * cd5 - g[8] * sd5;      // cos(d5 + t5)
        z[6] = cd6;
        z[7] = cd6 * cd7;
        z[8] = g[9] * cd7 * cd8;

        const float* w0 = W + t * 9;          // class 0 weights for this patch
        const float* w1 = W + FEAT + t * 9;   // class 1 weights
        #pragma unroll
        for (int k = 0; k < 9; k++) {
            s0 = fmaf(z[k], __ldg(w0 + k), s0);
            s1 = fmaf(z[k], __ldg(w1 + k), s1);
        }
    }

    // warp-level reduction of (s0, s1)
    #pragma unroll
    for (int off = 16; off > 0; off >>= 1) {
        s0 += __shfl_down_sync(0xffffffffu, s0, off);
        s1 += __shfl_down_sync(0xffffffffu, s1, off);
    }
    const int wid = t >> 5;
    if ((t & 31) == 0) { warp0[wid] = s0; warp1[wid] = s1; }
    __syncthreads();

    if (t == 0) {
        float l0 = bias[0], l1 = bias[1];
        #pragma unroll
        for (int i = 0; i < 6; i++) { l0 += warp0[i]; l1 += warp1[i]; }
        const float m   = fmaxf(l0, l1);
        const float lse = m + __logf(__expf(l0 - m) + __expf(l1 - m));
        float2 res = make_float2(l0 - lse, l1 - lse);
        *(float2*)(out + img * 2) = res;
    }
}

extern "C" void kernel_launch(void* const* d_in, const int* in_sizes, int n_in,
                              void* d_out, int out_size) {
    const float* x  = (const float*)d_in[0];
    const float* qp = (const float*)d_in[1];
    const float* W  = (const float*)d_in[2];
    const float* b  = (const float*)d_in[3];
    float* out = (float*)d_out;

    const int bsz = in_sizes[0] / IMG_PIX;   // 512
    quanv_fused_kernel<<<bsz, NTHREADS>>>(x, qp, W, b, out);
}